// round 6
// baseline (speedup 1.0000x reference)
#include <cuda_runtime.h>
#include <cuda_bf16.h>

// ---------------- static scratch ----------------
__device__ int g_node_off[1025];

__global__ void k_prefix(const int* __restrict__ bn, int B) {
    if (threadIdx.x == 0) {
        int acc = 0;
        g_node_off[0] = 0;
        for (int i = 0; i < B; ++i) { acc += bn[i]; g_node_off[i + 1] = acc; }
    }
}

// ---------------- fast path: column-strip private accumulation -----------
// CTA = (graph, node chunk). 8 warps; warp w owns columns [16w, 16w+16).
// Each warp has a PRIVATE smem accumulator (64 segs x 16 cols, stride 18
// floats) -> no cross-warp races, no cross-warp merge (disjoint columns).
// Hot loop: 32-node batches; lane = (node-group 0..3, slot 0..7); each lane
// preloads 8 float2 strip-chunks (LDG.64, MLP=8), then 8 iterations of
// shfl-broadcast seg/inv + LDS.64/FFMA/STS.64. Intra-warp same-seg
// collisions resolved exactly via __match_any_sync step-serialization.
#define SSTRIDE 18                 // floats per seg row (8B aligned, bank-rotating)
#define WACC (64 * SSTRIDE)        // 1152 floats = 4608B per warp

__global__ void __launch_bounds__(256) spp_strip_kernel(
    const float* __restrict__ feat,
    const int*   __restrict__ xy,
    float*       __restrict__ out,
    int G, int C)
{
    __shared__ float s_acc[8 * WACC];          // 36,864 B

    const int t    = threadIdx.x;
    const int w    = t >> 5;                   // warp = column strip
    const int lane = t & 31;
    const int grp4 = lane >> 3;                // node group 0..3
    const int slot = lane & 7;                 // float2 slot 0..7

    const int g     = blockIdx.x / C;          // graph id
    const int chunk = blockIdx.x % C;

    const int gbeg = g_node_off[g];
    const int glen = g_node_off[g + 1] - gbeg;
    const int cbeg = gbeg + (int)((long long)glen * chunk / C);
    const int cend = gbeg + (int)((long long)glen * (chunk + 1) / C);

    // zero accumulators
    float2* z = reinterpret_cast<float2*>(s_acc);
    #pragma unroll
    for (int i = t; i < 4 * WACC; i += 256) z[i] = make_float2(0.f, 0.f);
    __syncthreads();

    float* acc = s_acc + w * WACC;
    const unsigned FULL  = 0xffffffffu;
    const unsigned below = grp4 ? ((1u << (grp4 * 8)) - 1u) : 0u;
    const float*   fbase = feat + (size_t)w * 16 + (size_t)slot * 2;

    for (int base = cbeg; base < cend; base += 32) {
        const int cnt = (cend - base >= 32) ? 32 : (cend - base);
        const int nd  = base + ((lane < cnt) ? lane : (cnt - 1));

        const int rr = __ldg(&xy[3 * nd + 0]);
        const int cc = __ldg(&xy[3 * nd + 1]);
        const int dv = __ldg(&xy[3 * nd + 2]);
        int myseg = rr * G + cc;
        if (lane >= cnt) myseg = 64 + lane;     // out-of-range, never matches
        const float myinv = 1.0f / (float)dv;

        // preload the 8 strip rows this lane touches (MLP = 8, LDG.64)
        float2 vv[8];
        #pragma unroll
        for (int it = 0; it < 8; ++it) {
            const int nb   = it * 4 + grp4;
            const int node = base + ((nb < cnt) ? nb : (cnt - 1));
            vv[it] = __ldg(reinterpret_cast<const float2*>(fbase + (size_t)node * 128));
        }

        #pragma unroll
        for (int it = 0; it < 8; ++it) {
            const int   nb  = it * 4 + grp4;
            const int   seg = __shfl_sync(FULL, myseg, nb);
            const float inv = __shfl_sync(FULL, myinv, nb);
            const bool  act = (nb < cnt) & (seg < 64);

            const unsigned mm  = __match_any_sync(FULL, seg);
            const int      stp = __popc(mm & below) >> 3;

            float2 v = vv[it];
            v.x *= inv; v.y *= inv;
            float2* ap = reinterpret_cast<float2*>(acc + seg * SSTRIDE + slot * 2);

            if (__all_sync(FULL, stp == 0)) {    // common: 4 distinct segs
                if (act) {
                    float2 a = *ap;
                    a.x += v.x; a.y += v.y;
                    *ap = a;
                }
            } else {                             // rare: serialize colliders
                #pragma unroll
                for (int st = 0; st < 4; ++st) {
                    if (act && stp == st) {
                        float2 a = *ap;
                        a.x += v.x; a.y += v.y;
                        *ap = a;
                    }
                    __syncwarp();
                }
            }
        }
    }
    __syncwarp();

    // epilogue: each warp flushes its own strip (64 segs x 16 cols), RED.v2
    float* dstw = out + (size_t)g * 64 * 128 + (size_t)w * 16;
    #pragma unroll
    for (int i = lane; i < 512; i += 32) {
        const int seg = i >> 3, q = i & 7;
        float2 a = *reinterpret_cast<float2*>(acc + seg * SSTRIDE + q * 2);
        asm volatile("red.global.add.v2.f32 [%0], {%1, %2};"
                     :: "l"(dstw + (size_t)seg * 128 + q * 2), "f"(a.x), "f"(a.y)
                     : "memory");
    }
}

// ---------------- fallback path (round-2 kernel) ----------------
__device__ __forceinline__ int find_graph(const int* s_off, int B, int node) {
    int lo = 0, hi = B;
    while (hi - lo > 1) {
        int mid = (lo + hi) >> 1;
        if (s_off[mid] <= node) lo = mid; else hi = mid;
    }
    return lo;
}

__global__ void __launch_bounds__(256) spp_pool_fallback(
    const float* __restrict__ feat, const int* __restrict__ xy,
    float* __restrict__ out, int N, int D, int G, int B)
{
    extern __shared__ int s_off[];
    for (int i = threadIdx.x; i <= B; i += blockDim.x) s_off[i] = g_node_off[i];
    __syncthreads();

    const int lane   = threadIdx.x & 31;
    const int warp   = (blockIdx.x * blockDim.x + threadIdx.x) >> 5;
    const int nwarps = (gridDim.x * blockDim.x) >> 5;

    for (long long base = (long long)warp * 32; base < N;
         base += (long long)nwarps * 32) {
        long long mynode = base + lane;
        int nd = (mynode < N) ? (int)mynode : (N - 1);
        const int r  = __ldg(&xy[3 * nd + 0]);
        const int c  = __ldg(&xy[3 * nd + 1]);
        const int dv = __ldg(&xy[3 * nd + 2]);
        int gid = find_graph(s_off, B, nd);
        const int   myseg = (gid * G + r) * G + c;
        const float myinv = 1.0f / (float)dv;
        const int cnt = (N - base >= 32) ? 32 : (int)(N - base);

        for (int j = 0; j < cnt; ++j) {
            const int   seg = __shfl_sync(0xffffffffu, myseg, j);
            const float inv = __shfl_sync(0xffffffffu, myinv, j);
            const float* src = feat + ((size_t)(base + j)) * D;
            for (int d4 = lane; d4 * 4 < D; d4 += 32) {
                float4 v = __ldg(reinterpret_cast<const float4*>(src) + d4);
                v.x *= inv; v.y *= inv; v.z *= inv; v.w *= inv;
                float* dst = out + (size_t)seg * D + d4 * 4;
                asm volatile("red.global.add.v4.f32 [%0], {%1, %2, %3, %4};"
                             :: "l"(dst), "f"(v.x), "f"(v.y), "f"(v.z), "f"(v.w)
                             : "memory");
            }
        }
    }
}

extern "C" void kernel_launch(void* const* d_in, const int* in_sizes, int n_in,
                              void* d_out, int out_size) {
    const float* feat = (const float*)d_in[0];
    const int*   xy   = (const int*)d_in[1];
    const int*   bn   = (const int*)d_in[2];
    float*       out  = (float*)d_out;

    const int B = in_sizes[2];
    const int N = in_sizes[1] / 3;
    const int D = in_sizes[0] / N;
    const int S = out_size / D;        // B*G*G
    const int gg = S / B;
    int G = 1;
    while (G * G < gg) ++G;

    k_prefix<<<1, 32>>>(bn, B);

    // output accumulated via RED in both paths -> zero every replay
    cudaMemsetAsync(d_out, 0, (size_t)out_size * sizeof(float), 0);

    const bool fast = (D == 128) && (gg == 64) && (G == 8) &&
                      (S == B * 64) && (B <= 1024);

    if (fast) {
        int C = 3072 / B;              // ~3072 CTAs (B=64 -> C=48)
        if (C < 1) C = 1;
        spp_strip_kernel<<<B * C, 256>>>(feat, xy, out, G, C);
    } else {
        size_t smem = (size_t)(B + 1) * sizeof(int);
        long long batches = ((long long)N + 31) / 32;
        int blocks = (int)((batches + 7) / 8);
        if (blocks > 65535) blocks = 65535;
        spp_pool_fallback<<<blocks, 256, smem>>>(feat, xy, out, N, D, G, B);
    }
}

// round 8
// speedup vs baseline: 1.4394x; 1.4394x over previous
#include <cuda_runtime.h>
#include <cuda_bf16.h>

// ---------------- static scratch ----------------
__device__ int g_node_off[1025];

__global__ void k_prefix(const int* __restrict__ bn, int B) {
    if (threadIdx.x == 0) {
        int acc = 0;
        g_node_off[0] = 0;
        for (int i = 0; i < B; ++i) { acc += bn[i]; g_node_off[i + 1] = acc; }
    }
}

// ---------------- fast path ------------------------------------------------
// CTA = (graph, chunk); 4 warps, warp w owns 32-col slice [32w, 32w+32).
// EVERY warp walks ALL 32-node batches of the chunk (fix for R7: a node's
// slice-w columns can only be accumulated by warp w, so node partitioning
// across warps drops 3/4 of the sum).
// Warp-private accumulator: 64 segs x 32 floats (stride 32, conflict-free:
// each 8-lane phase of LDS.128/STS.128 touches one contiguous 128B row).
// Batches are double-buffered (meta + 8x LDG.128 prefetch). Collisions
// (node-groups with equal seg within one iteration) handled by leader/donor
// shfl merge -- exact, no serialization.
#define FULLM 0xffffffffu

struct Batch {
    int    seg;
    float  inv;
    float4 vv[8];
};

__device__ __forceinline__ void load_batch(
    Batch& b, const int* __restrict__ xy, const float* __restrict__ fbase,
    int base, int cend, int G, int lane, int grp)
{
    const int cnt = cend - base;                   // >= 1 (may exceed 32)
    const int l   = (lane < cnt) ? lane : (cnt - 1);
    const int nd  = base + l;
    const int rr  = __ldg(&xy[3 * nd + 0]);
    const int cc  = __ldg(&xy[3 * nd + 1]);
    const int dv  = __ldg(&xy[3 * nd + 2]);
    b.seg = (lane < cnt) ? (rr * G + cc) : (64 + lane);  // marker: never matches
    b.inv = 1.0f / (float)dv;

    #pragma unroll
    for (int it = 0; it < 8; ++it) {
        const int nb   = it * 4 + grp;
        const int node = base + ((nb < cnt) ? nb : (cnt - 1));
        b.vv[it] = __ldg(reinterpret_cast<const float4*>(fbase + (size_t)node * 128));
    }
}

__device__ __forceinline__ void process_batch(
    float* __restrict__ acc, const Batch& b,
    int base, int cend, int lane, int grp, int slot, unsigned below)
{
    const int cnt = (cend - base >= 32) ? 32 : (cend - base);

    #pragma unroll
    for (int it = 0; it < 8; ++it) {
        const int   nb  = it * 4 + grp;
        const int   seg = __shfl_sync(FULLM, b.seg, nb);
        const float inv = __shfl_sync(FULLM, b.inv, nb);
        const bool  act = (nb < cnt);

        float4 wv = b.vv[it];
        wv.x *= inv; wv.y *= inv; wv.z *= inv; wv.w *= inv;

        const unsigned mm     = __match_any_sync(FULLM, seg);
        const bool     leader = (mm & below) == 0u;

        const int sidx = act ? seg : 0;
        float4* ap = reinterpret_cast<float4*>(acc + sidx * 32 + slot * 4);

        if (__all_sync(FULLM, leader)) {           // ~91%: 4 distinct segs
            if (act) {
                float4 a = *ap;
                a.x += wv.x; a.y += wv.y; a.z += wv.z; a.w += wv.w;
                *ap = a;
            }
        } else {                                   // leader absorbs donors
            const float x1 = __shfl_down_sync(FULLM, wv.x, 8);
            const float y1 = __shfl_down_sync(FULLM, wv.y, 8);
            const float z1 = __shfl_down_sync(FULLM, wv.z, 8);
            const float w1 = __shfl_down_sync(FULLM, wv.w, 8);
            const float x2 = __shfl_down_sync(FULLM, wv.x, 16);
            const float y2 = __shfl_down_sync(FULLM, wv.y, 16);
            const float z2 = __shfl_down_sync(FULLM, wv.z, 16);
            const float w2 = __shfl_down_sync(FULLM, wv.w, 16);
            const float x3 = __shfl_down_sync(FULLM, wv.x, 24);
            const float y3 = __shfl_down_sync(FULLM, wv.y, 24);
            const float z3 = __shfl_down_sync(FULLM, wv.z, 24);
            const float w3 = __shfl_down_sync(FULLM, wv.w, 24);

            const bool c1 = (grp < 3) && ((mm >> ((lane + 8)  & 31)) & 1u);
            const bool c2 = (grp < 2) && ((mm >> ((lane + 16) & 31)) & 1u);
            const bool c3 = (grp < 1) && ((mm >> ((lane + 24) & 31)) & 1u);

            if (act && leader) {
                float4 a = *ap;
                a.x += wv.x + (c1 ? x1 : 0.f) + (c2 ? x2 : 0.f) + (c3 ? x3 : 0.f);
                a.y += wv.y + (c1 ? y1 : 0.f) + (c2 ? y2 : 0.f) + (c3 ? y3 : 0.f);
                a.z += wv.z + (c1 ? z1 : 0.f) + (c2 ? z2 : 0.f) + (c3 ? z3 : 0.f);
                a.w += wv.w + (c1 ? w1 : 0.f) + (c2 ? w2 : 0.f) + (c3 ? w3 : 0.f);
                *ap = a;
            }
        }
    }
}

__global__ void __launch_bounds__(128, 5) spp_pipe_kernel(
    const float* __restrict__ feat,
    const int*   __restrict__ xy,
    float*       __restrict__ out,
    int G, int C)
{
    __shared__ float s_acc[4 * 64 * 32];           // 32 KB, stride 32 (no pad)

    const int t    = threadIdx.x;
    const int w    = t >> 5;                       // warp = 32-col slice
    const int lane = t & 31;
    const int grp  = lane >> 3;                    // node group 0..3
    const int slot = lane & 7;                     // float4 slot 0..7
    const unsigned below = grp ? ((1u << (grp * 8)) - 1u) : 0u;

    const int g     = blockIdx.x / C;
    const int chunk = blockIdx.x % C;
    const int gbeg  = g_node_off[g];
    const int glen  = g_node_off[g + 1] - gbeg;
    const int cbeg  = gbeg + (int)((long long)glen * chunk / C);
    const int cend  = gbeg + (int)((long long)glen * (chunk + 1) / C);

    // zero accumulators
    float4* z = reinterpret_cast<float4*>(s_acc);
    #pragma unroll
    for (int i = t; i < 4 * 64 * 8; i += 128) z[i] = make_float4(0.f, 0.f, 0.f, 0.f);
    __syncthreads();

    float* acc = s_acc + w * 64 * 32;
    const float* fbase = feat + (size_t)w * 32 + (size_t)slot * 4;

    // each warp walks ALL batches of the chunk (step 32), double-buffered
    Batch A, B2;
    int base = cbeg;
    if (base < cend) {
        load_batch(A, xy, fbase, base, cend, G, lane, grp);
        for (;;) {
            const int base2 = base + 32;
            if (base2 < cend) {
                load_batch(B2, xy, fbase, base2, cend, G, lane, grp);
                process_batch(acc, A, base, cend, lane, grp, slot, below);
                const int base3 = base2 + 32;
                if (base3 < cend) {
                    load_batch(A, xy, fbase, base3, cend, G, lane, grp);
                    process_batch(acc, B2, base2, cend, lane, grp, slot, below);
                    base = base3;
                    continue;
                }
                process_batch(acc, B2, base2, cend, lane, grp, slot, below);
                break;
            }
            process_batch(acc, A, base, cend, lane, grp, slot, below);
            break;
        }
    }
    __syncwarp();

    // epilogue: each warp flushes its own 8KB slice via RED.v4
    float* dstw = out + (size_t)g * 64 * 128 + (size_t)w * 32;
    #pragma unroll
    for (int i = lane; i < 512; i += 32) {
        const int seg = i >> 3, q = i & 7;
        float4 a = *reinterpret_cast<float4*>(acc + seg * 32 + q * 4);
        asm volatile("red.global.add.v4.f32 [%0], {%1, %2, %3, %4};"
                     :: "l"(dstw + (size_t)seg * 128 + q * 4),
                        "f"(a.x), "f"(a.y), "f"(a.z), "f"(a.w)
                     : "memory");
    }
}

// ---------------- fallback path (round-2 kernel) ----------------
__device__ __forceinline__ int find_graph(const int* s_off, int B, int node) {
    int lo = 0, hi = B;
    while (hi - lo > 1) {
        int mid = (lo + hi) >> 1;
        if (s_off[mid] <= node) lo = mid; else hi = mid;
    }
    return lo;
}

__global__ void __launch_bounds__(256) spp_pool_fallback(
    const float* __restrict__ feat, const int* __restrict__ xy,
    float* __restrict__ out, int N, int D, int G, int B)
{
    extern __shared__ int s_off[];
    for (int i = threadIdx.x; i <= B; i += blockDim.x) s_off[i] = g_node_off[i];
    __syncthreads();

    const int lane   = threadIdx.x & 31;
    const int warp   = (blockIdx.x * blockDim.x + threadIdx.x) >> 5;
    const int nwarps = (gridDim.x * blockDim.x) >> 5;

    for (long long base = (long long)warp * 32; base < N;
         base += (long long)nwarps * 32) {
        long long mynode = base + lane;
        int nd = (mynode < N) ? (int)mynode : (N - 1);
        const int r  = __ldg(&xy[3 * nd + 0]);
        const int c  = __ldg(&xy[3 * nd + 1]);
        const int dv = __ldg(&xy[3 * nd + 2]);
        int gid = find_graph(s_off, B, nd);
        const int   myseg = (gid * G + r) * G + c;
        const float myinv = 1.0f / (float)dv;
        const int cnt = (N - base >= 32) ? 32 : (int)(N - base);

        for (int j = 0; j < cnt; ++j) {
            const int   seg = __shfl_sync(0xffffffffu, myseg, j);
            const float inv = __shfl_sync(0xffffffffu, myinv, j);
            const float* src = feat + ((size_t)(base + j)) * D;
            for (int d4 = lane; d4 * 4 < D; d4 += 32) {
                float4 v = __ldg(reinterpret_cast<const float4*>(src) + d4);
                v.x *= inv; v.y *= inv; v.z *= inv; v.w *= inv;
                float* dst = out + (size_t)seg * D + d4 * 4;
                asm volatile("red.global.add.v4.f32 [%0], {%1, %2, %3, %4};"
                             :: "l"(dst), "f"(v.x), "f"(v.y), "f"(v.z), "f"(v.w)
                             : "memory");
            }
        }
    }
}

extern "C" void kernel_launch(void* const* d_in, const int* in_sizes, int n_in,
                              void* d_out, int out_size) {
    const float* feat = (const float*)d_in[0];
    const int*   xy   = (const int*)d_in[1];
    const int*   bn   = (const int*)d_in[2];
    float*       out  = (float*)d_out;

    const int B = in_sizes[2];
    const int N = in_sizes[1] / 3;
    const int D = in_sizes[0] / N;
    const int S = out_size / D;        // B*G*G
    const int gg = S / B;
    int G = 1;
    while (G * G < gg) ++G;

    k_prefix<<<1, 32>>>(bn, B);

    // output accumulated via RED in both paths -> zero every replay
    cudaMemsetAsync(d_out, 0, (size_t)out_size * sizeof(float), 0);

    const bool fast = (D == 128) && (gg == 64) && (G == 8) &&
                      (S == B * 64) && (B <= 1024);

    if (fast) {
        int C = 704 / B;               // single wave at 5 CTAs/SM (B=64 -> 11)
        if (C < 1) C = 1;
        spp_pipe_kernel<<<B * C, 128>>>(feat, xy, out, G, C);
    } else {
        size_t smem = (size_t)(B + 1) * sizeof(int);
        long long batches = ((long long)N + 31) / 32;
        int blocks = (int)((batches + 7) / 8);
        if (blocks > 65535) blocks = 65535;
        spp_pool_fallback<<<blocks, 256, smem>>>(feat, xy, out, N, D, G, B);
    }
}

// round 9
// speedup vs baseline: 1.6149x; 1.1219x over previous
#include <cuda_runtime.h>
#include <cuda_bf16.h>

// ---------------- static scratch ----------------
__device__ int g_node_off[1025];

__global__ void k_prefix(const int* __restrict__ bn, int B) {
    if (threadIdx.x == 0) {
        int acc = 0;
        g_node_off[0] = 0;
        for (int i = 0; i < B; ++i) { acc += bn[i]; g_node_off[i + 1] = acc; }
    }
}

// ---------------- fast path ------------------------------------------------
// CTA = (graph, chunk); 4 warps, warp w owns 32-col slice [32w, 32w+32).
// Every warp walks all 32-node batches of the chunk.
// Per-warp private accumulator: 64 segs x 32 floats (stride 32, conflict-free).
//
// R9 split: per batch,
//   load  = LDG issue only (xy meta + 8x LDG.128 feature rows)
//   meta  = ALL warp intrinsics (shfl seg/inv broadcast, match, vote, donor
//           merge, inv-scaling) -- independent across the 8 iterations, so
//           their 26-30cyc latencies pipeline; runs overlapped w/ prev RMW.
//           Output: scaled+merged vv[8], segs packed 8x8b in 2 regs, pred mask.
//   rmw   = 8x predicated {LDS.128, 4xFADD, STS.128} -- short alias-ordered
//           chain, no MIO ops.
#define FULLM 0xffffffffu

struct Batch {
    int      seg;        // this lane's node seg (64+lane marker if inactive)
    float    inv;
    float4   vv[8];      // after meta: scaled + donor-merged
    unsigned sp0, sp1;   // after meta: segs of iters 0..3 / 4..7, 8b each
    unsigned pmask;      // after meta: bit it = (active && leader)
};

__device__ __forceinline__ void load_batch(
    Batch& b, const int* __restrict__ xy, const float* __restrict__ fbase,
    int base, int cend, int G, int lane, int grp)
{
    const int cnt = cend - base;                   // >= 1 (may exceed 32)
    const int l   = (lane < cnt) ? lane : (cnt - 1);
    const int nd  = base + l;
    const int rr  = __ldg(&xy[3 * nd + 0]);
    const int cc  = __ldg(&xy[3 * nd + 1]);
    const int dv  = __ldg(&xy[3 * nd + 2]);
    b.seg = (lane < cnt) ? (rr * G + cc) : (64 + lane);  // marker never matches
    b.inv = 1.0f / (float)dv;

    #pragma unroll
    for (int it = 0; it < 8; ++it) {
        const int nb   = it * 4 + grp;
        const int node = base + ((nb < cnt) ? nb : (cnt - 1));
        b.vv[it] = __ldg(reinterpret_cast<const float4*>(fbase + (size_t)node * 128));
    }
}

__device__ __forceinline__ void meta_batch(
    Batch& b, int base, int cend, int lane, int grp, unsigned below)
{
    const int cnt = (cend - base >= 32) ? 32 : (cend - base);
    unsigned pm = 0, s0 = 0, s1 = 0;

    #pragma unroll
    for (int it = 0; it < 8; ++it) {
        const int   nb  = it * 4 + grp;
        const int   seg = __shfl_sync(FULLM, b.seg, nb);
        const float inv = __shfl_sync(FULLM, b.inv, nb);
        const bool  act = (nb < cnt);

        float4 wv = b.vv[it];
        wv.x *= inv; wv.y *= inv; wv.z *= inv; wv.w *= inv;

        const unsigned mm     = __match_any_sync(FULLM, seg);
        const bool     leader = (mm & below) == 0u;

        if (!__all_sync(FULLM, leader)) {          // ~9%: donor merge
            const float x1 = __shfl_down_sync(FULLM, wv.x, 8);
            const float y1 = __shfl_down_sync(FULLM, wv.y, 8);
            const float z1 = __shfl_down_sync(FULLM, wv.z, 8);
            const float w1 = __shfl_down_sync(FULLM, wv.w, 8);
            const float x2 = __shfl_down_sync(FULLM, wv.x, 16);
            const float y2 = __shfl_down_sync(FULLM, wv.y, 16);
            const float z2 = __shfl_down_sync(FULLM, wv.z, 16);
            const float w2 = __shfl_down_sync(FULLM, wv.w, 16);
            const float x3 = __shfl_down_sync(FULLM, wv.x, 24);
            const float y3 = __shfl_down_sync(FULLM, wv.y, 24);
            const float z3 = __shfl_down_sync(FULLM, wv.z, 24);
            const float w3 = __shfl_down_sync(FULLM, wv.w, 24);

            const bool c1 = (grp < 3) && ((mm >> ((lane + 8)  & 31)) & 1u);
            const bool c2 = (grp < 2) && ((mm >> ((lane + 16) & 31)) & 1u);
            const bool c3 = (grp < 1) && ((mm >> ((lane + 24) & 31)) & 1u);

            wv.x += (c1 ? x1 : 0.f) + (c2 ? x2 : 0.f) + (c3 ? x3 : 0.f);
            wv.y += (c1 ? y1 : 0.f) + (c2 ? y2 : 0.f) + (c3 ? y3 : 0.f);
            wv.z += (c1 ? z1 : 0.f) + (c2 ? z2 : 0.f) + (c3 ? z3 : 0.f);
            wv.w += (c1 ? w1 : 0.f) + (c2 ? w2 : 0.f) + (c3 ? w3 : 0.f);
        }
        b.vv[it] = wv;

        const unsigned sb = (unsigned)(seg & 63) << ((it & 3) * 8);
        if (it < 4) s0 |= sb; else s1 |= sb;
        if (act && leader) pm |= (1u << it);
    }
    b.sp0 = s0; b.sp1 = s1; b.pmask = pm;
}

__device__ __forceinline__ void rmw_batch(
    float* __restrict__ acc, const Batch& b, int slot)
{
    #pragma unroll
    for (int it = 0; it < 8; ++it) {
        if (b.pmask & (1u << it)) {
            const unsigned sp  = (it < 4) ? b.sp0 : b.sp1;
            const int      seg = (sp >> ((it & 3) * 8)) & 0xFF;
            float4* ap = reinterpret_cast<float4*>(acc + seg * 32 + slot * 4);
            float4 a = *ap;
            const float4 v = b.vv[it];
            a.x += v.x; a.y += v.y; a.z += v.z; a.w += v.w;
            *ap = a;
        }
    }
}

__global__ void __launch_bounds__(128, 5) spp_pipe_kernel(
    const float* __restrict__ feat,
    const int*   __restrict__ xy,
    float*       __restrict__ out,
    int G, int C)
{
    __shared__ float s_acc[4 * 64 * 32];           // 32 KB, stride 32 (no pad)

    const int t    = threadIdx.x;
    const int w    = t >> 5;                       // warp = 32-col slice
    const int lane = t & 31;
    const int grp  = lane >> 3;                    // node group 0..3
    const int slot = lane & 7;                     // float4 slot 0..7
    const unsigned below = grp ? ((1u << (grp * 8)) - 1u) : 0u;

    const int g     = blockIdx.x / C;
    const int chunk = blockIdx.x % C;
    const int gbeg  = g_node_off[g];
    const int glen  = g_node_off[g + 1] - gbeg;
    const int cbeg  = gbeg + (int)((long long)glen * chunk / C);
    const int cend  = gbeg + (int)((long long)glen * (chunk + 1) / C);

    // zero accumulators
    float4* z = reinterpret_cast<float4*>(s_acc);
    #pragma unroll
    for (int i = t; i < 4 * 64 * 8; i += 128) z[i] = make_float4(0.f, 0.f, 0.f, 0.f);
    __syncthreads();

    float* acc = s_acc + w * 64 * 32;
    const float* fbase = feat + (size_t)w * 32 + (size_t)slot * 4;

    // pipeline: load(b+1) -> rmw(b) -> meta(b+1)
    Batch A, B2;
    int base = cbeg;
    if (base < cend) {
        load_batch(A, xy, fbase, base, cend, G, lane, grp);
        meta_batch(A, base, cend, lane, grp, below);
        for (;;) {
            const int base2 = base + 32;
            if (base2 < cend) {
                load_batch(B2, xy, fbase, base2, cend, G, lane, grp);
                rmw_batch(acc, A, slot);
                meta_batch(B2, base2, cend, lane, grp, below);
                const int base3 = base2 + 32;
                if (base3 < cend) {
                    load_batch(A, xy, fbase, base3, cend, G, lane, grp);
                    rmw_batch(acc, B2, slot);
                    meta_batch(A, base3, cend, lane, grp, below);
                    base = base3;
                    continue;
                }
                rmw_batch(acc, B2, slot);
                break;
            }
            rmw_batch(acc, A, slot);
            break;
        }
    }
    __syncwarp();

    // epilogue: each warp flushes its own 8KB slice via RED.v4
    float* dstw = out + (size_t)g * 64 * 128 + (size_t)w * 32;
    #pragma unroll
    for (int i = lane; i < 512; i += 32) {
        const int seg = i >> 3, q = i & 7;
        float4 a = *reinterpret_cast<float4*>(acc + seg * 32 + q * 4);
        asm volatile("red.global.add.v4.f32 [%0], {%1, %2, %3, %4};"
                     :: "l"(dstw + (size_t)seg * 128 + q * 4),
                        "f"(a.x), "f"(a.y), "f"(a.z), "f"(a.w)
                     : "memory");
    }
}

// ---------------- fallback path (round-2 kernel) ----------------
__device__ __forceinline__ int find_graph(const int* s_off, int B, int node) {
    int lo = 0, hi = B;
    while (hi - lo > 1) {
        int mid = (lo + hi) >> 1;
        if (s_off[mid] <= node) lo = mid; else hi = mid;
    }
    return lo;
}

__global__ void __launch_bounds__(256) spp_pool_fallback(
    const float* __restrict__ feat, const int* __restrict__ xy,
    float* __restrict__ out, int N, int D, int G, int B)
{
    extern __shared__ int s_off[];
    for (int i = threadIdx.x; i <= B; i += blockDim.x) s_off[i] = g_node_off[i];
    __syncthreads();

    const int lane   = threadIdx.x & 31;
    const int warp   = (blockIdx.x * blockDim.x + threadIdx.x) >> 5;
    const int nwarps = (gridDim.x * blockDim.x) >> 5;

    for (long long base = (long long)warp * 32; base < N;
         base += (long long)nwarps * 32) {
        long long mynode = base + lane;
        int nd = (mynode < N) ? (int)mynode : (N - 1);
        const int r  = __ldg(&xy[3 * nd + 0]);
        const int c  = __ldg(&xy[3 * nd + 1]);
        const int dv = __ldg(&xy[3 * nd + 2]);
        int gid = find_graph(s_off, B, nd);
        const int   myseg = (gid * G + r) * G + c;
        const float myinv = 1.0f / (float)dv;
        const int cnt = (N - base >= 32) ? 32 : (int)(N - base);

        for (int j = 0; j < cnt; ++j) {
            const int   seg = __shfl_sync(0xffffffffu, myseg, j);
            const float inv = __shfl_sync(0xffffffffu, myinv, j);
            const float* src = feat + ((size_t)(base + j)) * D;
            for (int d4 = lane; d4 * 4 < D; d4 += 32) {
                float4 v = __ldg(reinterpret_cast<const float4*>(src) + d4);
                v.x *= inv; v.y *= inv; v.z *= inv; v.w *= inv;
                float* dst = out + (size_t)seg * D + d4 * 4;
                asm volatile("red.global.add.v4.f32 [%0], {%1, %2, %3, %4};"
                             :: "l"(dst), "f"(v.x), "f"(v.y), "f"(v.z), "f"(v.w)
                             : "memory");
            }
        }
    }
}

extern "C" void kernel_launch(void* const* d_in, const int* in_sizes, int n_in,
                              void* d_out, int out_size) {
    const float* feat = (const float*)d_in[0];
    const int*   xy   = (const int*)d_in[1];
    const int*   bn   = (const int*)d_in[2];
    float*       out  = (float*)d_out;

    const int B = in_sizes[2];
    const int N = in_sizes[1] / 3;
    const int D = in_sizes[0] / N;
    const int S = out_size / D;        // B*G*G
    const int gg = S / B;
    int G = 1;
    while (G * G < gg) ++G;

    k_prefix<<<1, 32>>>(bn, B);

    // output accumulated via RED in both paths -> zero every replay
    cudaMemsetAsync(d_out, 0, (size_t)out_size * sizeof(float), 0);

    const bool fast = (D == 128) && (gg == 64) && (G == 8) &&
                      (S == B * 64) && (B <= 1024);

    if (fast) {
        int C = 704 / B;               // single wave at 5 CTAs/SM (B=64 -> 11)
        if (C < 1) C = 1;
        spp_pipe_kernel<<<B * C, 128>>>(feat, xy, out, G, C);
    } else {
        size_t smem = (size_t)(B + 1) * sizeof(int);
        long long batches = ((long long)N + 31) / 32;
        int blocks = (int)((batches + 7) / 8);
        if (blocks > 65535) blocks = 65535;
        spp_pool_fallback<<<blocks, 256, smem>>>(feat, xy, out, N, D, G, B);
    }
}